// round 15
// baseline (speedup 1.0000x reference)
#include <cuda_runtime.h>
#include <cstdint>

#define Hc 128
#define Nc 128
#define Lc 2048
#define NF 4096   // FFT length (>= 2*Lc - 1)

// Transposed scratch: g_KlT[l * Hc + h] = Kl[h, l]   (1 MB)
__device__ float g_KlT[Lc * Hc];
// Twiddle quarter-table: g_tw[t] = exp(-2*pi*i * t / 4096), t in [0,1024)
__device__ float2 g_tw[1024];

// ---------------------------------------------------------------------------
// Kernel 1: KlT[l,h] = sum_n C[h,n] * K[l,h,n]   (verified R13 version)
// One block per l; contiguous 64KB slab; MLP=16 streaming loads; one
// contiguous 512B store. Blocks 0..3 additionally build the twiddle table.
// ---------------------------------------------------------------------------
__global__ __launch_bounds__(256) void kl_synth_kernel(
    const float* __restrict__ K,   // (L,H,N)
    const float* __restrict__ C)   // (H,N)
{
    __shared__ float sKl[Hc];          // 512B stage

    const int l    = blockIdx.x;
    const int warp = threadIdx.x >> 5;
    const int lane = threadIdx.x & 31;
    const int h0   = warp * 16;

    // twiddle build (blocks 0..3 cover t in [0,1024))
    if (l < 4) {
        const int t = l * 256 + threadIdx.x;
        const float ang = (-2.0f * 3.14159265358979323846f / (float)NF) * (float)t;
        float sn, cs;
        sincosf(ang, &sn, &cs);
        g_tw[t] = make_float2(cs, sn);
    }

    const float4* Kl4 = reinterpret_cast<const float4*>(K + (size_t)l * (Hc * Nc));

    float4 kv[16];
    #pragma unroll
    for (int r = 0; r < 16; ++r)
        kv[r] = __ldcs(Kl4 + (h0 + r) * (Nc / 4) + lane);

    float s[16];
    #pragma unroll
    for (int r = 0; r < 16; ++r) {
        const float4 c4 = reinterpret_cast<const float4*>(C + (h0 + r) * Nc)[lane];
        s[r] = c4.x * kv[r].x + c4.y * kv[r].y + c4.z * kv[r].z + c4.w * kv[r].w;
    }
    #pragma unroll
    for (int r = 0; r < 16; ++r) {
        #pragma unroll
        for (int o = 16; o > 0; o >>= 1)
            s[r] += __shfl_xor_sync(0xFFFFFFFFu, s[r], o);
    }
    if (lane == 0) {
        #pragma unroll
        for (int r = 0; r < 16; ++r) sKl[h0 + r] = s[r];
    }
    __syncthreads();

    if (threadIdx.x < 128)
        g_KlT[l * Hc + threadIdx.x] = sKl[threadIdx.x];
}

// ---------------------------------------------------------------------------
// full twiddle lookup with quarter-table symmetry:
//   t in [0,2048);  W[t+1024] = W[t] * (-i) = (W.y, -W.x)
// ---------------------------------------------------------------------------
__device__ __forceinline__ float2 twiddle(const float2* stw, int t) {
    float2 w = stw[t & 1023];
    if (t & 1024) w = make_float2(w.y, -w.x);
    return w;
}
__device__ __forceinline__ float2 cmul(float2 a, float2 b) {
    return make_float2(a.x * b.x - a.y * b.y, a.x * b.y + a.y * b.x);
}

// ---------------------------------------------------------------------------
// Kernel 2: FFT convolution, one block (256 thr) per channel h.
//   z = u_pad + i*k_pad  (length 4096)
//   forward DIF FFT (natural in -> bit-reversed out), in-place
//   Hermitian unpack  U=(Z[f]+conj(Z[N-f]))/2, K=-i/2*(Z[f]-conj(Z[N-f]))
//   Y = U*K written back at bit-reversed positions (pairs disjoint)
//   inverse DIT FFT (bit-reversed in -> natural out), conj twiddles
//   y[t] = Re(x[t+1023])/N + D[h]*u[t]
// smem: 32KB data + 8KB twiddles = 40KB.
// ---------------------------------------------------------------------------
__global__ __launch_bounds__(256) void fftconv_kernel(
    const float* __restrict__ u,   // (H,L)
    const float* __restrict__ D,   // (H,)
    float* __restrict__ y)         // (H,L)
{
    __shared__ float2 sd[NF];      // 32 KB
    __shared__ float2 stw[1024];   // 8 KB

    const int h   = blockIdx.x;
    const int tid = threadIdx.x;

    // twiddles -> smem (coalesced)
    #pragma unroll
    for (int r = 0; r < 4; ++r)
        stw[tid + 256 * r] = g_tw[tid + 256 * r];

    // load z = u + i*k  (k from transposed KlT column h, L2-resident)
    const float* uh = u + h * Lc;
    for (int n = tid; n < Lc; n += 256)
        sd[n] = make_float2(uh[n], g_KlT[n * Hc + h]);
    for (int n = Lc + tid; n < NF; n += 256)
        sd[n] = make_float2(0.0f, 0.0f);
    __syncthreads();

    // ---- forward DIF: stage s, span len = NF>>s, half = 1<<(11-s) ----
    for (int s = 0; s < 12; ++s) {
        const int hb = 11 - s;
        #pragma unroll
        for (int r = 0; r < 8; ++r) {
            const int p  = tid + 256 * r;
            const int j  = p & ((1 << hb) - 1);
            const int g  = p >> hb;
            const int i0 = (g << (hb + 1)) | j;
            const int i1 = i0 + (1 << hb);
            const float2 a = sd[i0];
            const float2 b = sd[i1];
            sd[i0] = make_float2(a.x + b.x, a.y + b.y);
            const float2 d = make_float2(a.x - b.x, a.y - b.y);
            sd[i1] = cmul(d, twiddle(stw, j << s));
        }
        __syncthreads();
    }

    // ---- Hermitian unpack + pointwise multiply (bit-reversed order) ----
    for (int f = tid; f <= NF / 2; f += 256) {
        const int ia = __brev(f) >> 20;                       // 12-bit rev
        const int ib = __brev((NF - f) & (NF - 1)) >> 20;
        const float2 Za = sd[ia];
        const float2 Zb = sd[ib];
        const float2 U  = make_float2(0.5f * (Za.x + Zb.x), 0.5f * (Za.y - Zb.y));
        const float2 Kv = make_float2(0.5f * (Za.y + Zb.y), 0.5f * (Zb.x - Za.x));
        const float2 Y  = cmul(U, Kv);
        sd[ia] = Y;
        sd[ib] = make_float2(Y.x, -Y.y);                      // conj(Y)
    }
    __syncthreads();

    // ---- inverse DIT: len = 2 first (s=11) up to 4096 (s=0) ----
    for (int s = 11; s >= 0; --s) {
        const int hb = 11 - s;
        #pragma unroll
        for (int r = 0; r < 8; ++r) {
            const int p  = tid + 256 * r;
            const int j  = p & ((1 << hb) - 1);
            const int g  = p >> hb;
            const int i0 = (g << (hb + 1)) | j;
            const int i1 = i0 + (1 << hb);
            float2 w = twiddle(stw, j << s);
            w.y = -w.y;                                       // conjugate
            const float2 a = sd[i0];
            const float2 b = cmul(sd[i1], w);
            sd[i0] = make_float2(a.x + b.x, a.y + b.y);
            sd[i1] = make_float2(a.x - b.x, a.y - b.y);
        }
        __syncthreads();
    }

    // ---- 'same' slice + 1/N scale + skip connection ----
    const float dh    = D[h];
    const float scale = 1.0f / (float)NF;
    for (int t = tid; t < Lc; t += 256)
        y[h * Lc + t] = sd[t + 1023].x * scale + dh * uh[t];
}

// ---------------------------------------------------------------------------
extern "C" void kernel_launch(void* const* d_in, const int* in_sizes, int n_in,
                              void* d_out, int out_size)
{
    const float* u = nullptr;
    const float* C = nullptr;
    const float* D = nullptr;
    const float* K = nullptr;
    for (int i = 0; i < n_in; ++i) {
        switch (in_sizes[i]) {
            case Hc * Lc:  u = (const float*)d_in[i]; break;
            case Hc * Nc:  C = (const float*)d_in[i]; break;
            case Hc:       D = (const float*)d_in[i]; break;
            default:
                if (in_sizes[i] == Lc * Hc * Nc) K = (const float*)d_in[i];
                break;
        }
    }

    float* y = (float*)d_out;

    kl_synth_kernel<<<Lc, 256>>>(K, C);   // also builds twiddle table
    fftconv_kernel<<<Hc, 256>>>(u, D, y);
}

// round 16
// speedup vs baseline: 1.1599x; 1.1599x over previous
#include <cuda_runtime.h>
#include <cstdint>

#define Hc 128
#define Nc 128
#define Lc 2048
#define NF 4096   // FFT length (>= 2*Lc - 1)

// Transposed scratch: g_KlT[l * Hc + h] = Kl[h, l]   (1 MB)
__device__ float g_KlT[Lc * Hc];
// Twiddle quarter-table: g_tw[t] = exp(-2*pi*i * t / 4096), t in [0,1024)
__device__ float2 g_tw[1024];

// ---------------------------------------------------------------------------
// Kernel 1: KlT[l,h] = sum_n C[h,n] * K[l,h,n]   (verified R13 version)
// ---------------------------------------------------------------------------
__global__ __launch_bounds__(256) void kl_synth_kernel(
    const float* __restrict__ K,   // (L,H,N)
    const float* __restrict__ C)   // (H,N)
{
    __shared__ float sKl[Hc];

    const int l    = blockIdx.x;
    const int warp = threadIdx.x >> 5;
    const int lane = threadIdx.x & 31;
    const int h0   = warp * 16;

    if (l < 4) {
        const int t = l * 256 + threadIdx.x;
        const float ang = (-2.0f * 3.14159265358979323846f / (float)NF) * (float)t;
        float sn, cs;
        sincosf(ang, &sn, &cs);
        g_tw[t] = make_float2(cs, sn);
    }

    const float4* Kl4 = reinterpret_cast<const float4*>(K + (size_t)l * (Hc * Nc));

    float4 kv[16];
    #pragma unroll
    for (int r = 0; r < 16; ++r)
        kv[r] = __ldcs(Kl4 + (h0 + r) * (Nc / 4) + lane);

    float s[16];
    #pragma unroll
    for (int r = 0; r < 16; ++r) {
        const float4 c4 = reinterpret_cast<const float4*>(C + (h0 + r) * Nc)[lane];
        s[r] = c4.x * kv[r].x + c4.y * kv[r].y + c4.z * kv[r].z + c4.w * kv[r].w;
    }
    #pragma unroll
    for (int r = 0; r < 16; ++r) {
        #pragma unroll
        for (int o = 16; o > 0; o >>= 1)
            s[r] += __shfl_xor_sync(0xFFFFFFFFu, s[r], o);
    }
    if (lane == 0) {
        #pragma unroll
        for (int r = 0; r < 16; ++r) sKl[h0 + r] = s[r];
    }
    __syncthreads();

    if (threadIdx.x < 128)
        g_KlT[l * Hc + threadIdx.x] = sKl[threadIdx.x];
}

// ---------------------------------------------------------------------------
__device__ __forceinline__ float2 twiddle(const float2* stw, int t) {
    float2 w = stw[t & 1023];
    if (t & 1024) w = make_float2(w.y, -w.x);   // W[t+1024] = W[t] * (-i)
    return w;
}
__device__ __forceinline__ float2 cmul(float2 a, float2 b) {
    return make_float2(a.x * b.x - a.y * b.y, a.x * b.y + a.y * b.x);
}
__device__ __forceinline__ float2 cadd(float2 a, float2 b) {
    return make_float2(a.x + b.x, a.y + b.y);
}
__device__ __forceinline__ float2 csub(float2 a, float2 b) {
    return make_float2(a.x - b.x, a.y - b.y);
}

// ---------------------------------------------------------------------------
// Kernel 2: FFT convolution with FUSED radix-2 stage pairs.
//   forward: 6 fused stages (12 radix-2 DIF stages), natural -> bit-rev
//   unpack + pointwise in bit-rev order
//   inverse: 6 fused stages (12 radix-2 DIT stages), bit-rev -> natural
// Per fused stage each thread owns 4 disjoint quartets; all 16 loads batched
// before compute, all 16 stores after -> MLP=16, no false serialization.
// 14 barriers total (vs 25 in R15). smem 40KB.
// ---------------------------------------------------------------------------
__global__ __launch_bounds__(256) void fftconv_kernel(
    const float* __restrict__ u,   // (H,L)
    const float* __restrict__ D,   // (H,)
    float* __restrict__ y)         // (H,L)
{
    __shared__ float2 sd[NF];      // 32 KB
    __shared__ float2 stw[1024];   // 8 KB

    const int h   = blockIdx.x;
    const int tid = threadIdx.x;

    #pragma unroll
    for (int r = 0; r < 4; ++r)
        stw[tid + 256 * r] = g_tw[tid + 256 * r];

    // load z = u + i*k
    const float* uh = u + h * Lc;
    for (int n = tid; n < Lc; n += 256)
        sd[n] = make_float2(uh[n], g_KlT[n * Hc + h]);
    for (int n = Lc + tid; n < NF; n += 256)
        sd[n] = make_float2(0.0f, 0.0f);
    __syncthreads();

    // ---- forward: fused DIF stage pairs f=0..5 (radix-2 stages 2f, 2f+1) --
    #pragma unroll 1
    for (int f = 0; f < 6; ++f) {
        const int shq = 10 - 2 * f;          // log2(q)
        const int q   = 1 << shq;
        const int s   = 2 * f;

        int    mm[4];
        float2 x0[4], x1[4], x2[4], x3[4];
        float2 t1[4], t3[4];

        #pragma unroll
        for (int r = 0; r < 4; ++r) {
            const int p = tid + 256 * r;
            const int j = p & (q - 1);
            const int g = p >> shq;
            const int m = (g << (shq + 2)) | j;
            mm[r] = m;
            x0[r] = sd[m];
            x1[r] = sd[m + q];
            x2[r] = sd[m + 2 * q];
            x3[r] = sd[m + 3 * q];
            t1[r] = twiddle(stw, j << s);
            t3[r] = twiddle(stw, j << (s + 1));
        }
        #pragma unroll
        for (int r = 0; r < 4; ++r) {
            const float2 t2 = make_float2(t1[r].y, -t1[r].x);   // t1 * (-i)
            // radix-2 stage s  (pairs distance 2q)
            const float2 u0 = cadd(x0[r], x2[r]);
            const float2 v0 = cmul(csub(x0[r], x2[r]), t1[r]);
            const float2 u1 = cadd(x1[r], x3[r]);
            const float2 v1 = cmul(csub(x1[r], x3[r]), t2);
            // radix-2 stage s+1 (pairs distance q)
            x0[r] = cadd(u0, u1);
            x1[r] = cmul(csub(u0, u1), t3[r]);
            x2[r] = cadd(v0, v1);
            x3[r] = cmul(csub(v0, v1), t3[r]);
        }
        #pragma unroll
        for (int r = 0; r < 4; ++r) {
            const int m = mm[r];
            sd[m]         = x0[r];
            sd[m + q]     = x1[r];
            sd[m + 2 * q] = x2[r];
            sd[m + 3 * q] = x3[r];
        }
        __syncthreads();
    }

    // ---- Hermitian unpack + pointwise multiply (bit-reversed order) ----
    for (int f = tid; f <= NF / 2; f += 256) {
        const int ia = __brev(f) >> 20;                       // 12-bit rev
        const int ib = __brev((NF - f) & (NF - 1)) >> 20;
        const float2 Za = sd[ia];
        const float2 Zb = sd[ib];
        const float2 U  = make_float2(0.5f * (Za.x + Zb.x), 0.5f * (Za.y - Zb.y));
        const float2 Kv = make_float2(0.5f * (Za.y + Zb.y), 0.5f * (Zb.x - Za.x));
        const float2 Y  = cmul(U, Kv);
        sd[ia] = Y;
        sd[ib] = make_float2(Y.x, -Y.y);                      // conj(Y)
    }
    __syncthreads();

    // ---- inverse: fused DIT stage pairs f=0..5 (radix-2 stages 11-2f,10-2f)
    #pragma unroll 1
    for (int f = 0; f < 6; ++f) {
        const int shq = 2 * f;               // log2(qA)
        const int q   = 1 << shq;
        const int sA  = 11 - 2 * f;
        const int sB  = 10 - 2 * f;

        int    mm[4];
        float2 x0[4], x1[4], x2[4], x3[4];
        float2 wA[4], wB[4];

        #pragma unroll
        for (int r = 0; r < 4; ++r) {
            const int p = tid + 256 * r;
            const int j = p & (q - 1);
            const int g = p >> shq;
            const int m = (g << (shq + 2)) | j;
            mm[r] = m;
            x0[r] = sd[m];
            x1[r] = sd[m + q];
            x2[r] = sd[m + 2 * q];
            x3[r] = sd[m + 3 * q];
            float2 a = twiddle(stw, j << sA);  a.y = -a.y;    // conj
            float2 b = twiddle(stw, j << sB);  b.y = -b.y;    // conj
            wA[r] = a;
            wB[r] = b;
        }
        #pragma unroll
        for (int r = 0; r < 4; ++r) {
            const float2 wB2 = make_float2(-wB[r].y, wB[r].x);  // wB * (+i)
            // radix-2 DIT stage sA (pairs distance q)
            const float2 b1 = cmul(x1[r], wA[r]);
            const float2 y0 = cadd(x0[r], b1);
            const float2 y1 = csub(x0[r], b1);
            const float2 b3 = cmul(x3[r], wA[r]);
            const float2 y2 = cadd(x2[r], b3);
            const float2 y3 = csub(x2[r], b3);
            // radix-2 DIT stage sB (pairs distance 2q)
            const float2 c2 = cmul(y2, wB[r]);
            x0[r] = cadd(y0, c2);
            x2[r] = csub(y0, c2);
            const float2 c3 = cmul(y3, wB2);
            x1[r] = cadd(y1, c3);
            x3[r] = csub(y1, c3);
        }
        #pragma unroll
        for (int r = 0; r < 4; ++r) {
            const int m = mm[r];
            sd[m]         = x0[r];
            sd[m + q]     = x1[r];
            sd[m + 2 * q] = x2[r];
            sd[m + 3 * q] = x3[r];
        }
        __syncthreads();
    }

    // ---- 'same' slice + 1/N scale + skip connection ----
    const float dh    = D[h];
    const float scale = 1.0f / (float)NF;
    for (int t = tid; t < Lc; t += 256)
        y[h * Lc + t] = sd[t + 1023].x * scale + dh * uh[t];
}

// ---------------------------------------------------------------------------
extern "C" void kernel_launch(void* const* d_in, const int* in_sizes, int n_in,
                              void* d_out, int out_size)
{
    const float* u = nullptr;
    const float* C = nullptr;
    const float* D = nullptr;
    const float* K = nullptr;
    for (int i = 0; i < n_in; ++i) {
        switch (in_sizes[i]) {
            case Hc * Lc:  u = (const float*)d_in[i]; break;
            case Hc * Nc:  C = (const float*)d_in[i]; break;
            case Hc:       D = (const float*)d_in[i]; break;
            default:
                if (in_sizes[i] == Lc * Hc * Nc) K = (const float*)d_in[i];
                break;
        }
    }

    float* y = (float*)d_out;

    kl_synth_kernel<<<Lc, 256>>>(K, C);   // also builds twiddle table
    fftconv_kernel<<<Hc, 256>>>(u, D, y);
}

// round 17
// speedup vs baseline: 1.3807x; 1.1903x over previous
#include <cuda_runtime.h>
#include <cstdint>

#define Hc 128
#define Nc 128
#define Lc 2048
#define NF 4096
#define LOC(n) ((n) + ((n) >> 4))   // smem skew: <=2-way conflicts all strides

// Transposed scratch: g_KlT[l * Hc + h] = Kl[h, l]   (1 MB)
__device__ float g_KlT[Lc * Hc];
// Twiddle quarter-table: g_tw[t] = exp(-2*pi*i * t / 4096), t in [0,1024)
__device__ float2 g_tw[1024];

// ---------------------------------------------------------------------------
// Kernel 1: KlT[l,h] = sum_n C[h,n] * K[l,h,n]   (verified R13 version)
// ---------------------------------------------------------------------------
__global__ __launch_bounds__(256) void kl_synth_kernel(
    const float* __restrict__ K,   // (L,H,N)
    const float* __restrict__ C)   // (H,N)
{
    __shared__ float sKl[Hc];

    const int l    = blockIdx.x;
    const int warp = threadIdx.x >> 5;
    const int lane = threadIdx.x & 31;
    const int h0   = warp * 16;

    if (l < 4) {
        const int t = l * 256 + threadIdx.x;
        const float ang = (-2.0f * 3.14159265358979323846f / (float)NF) * (float)t;
        float sn, cs;
        sincosf(ang, &sn, &cs);
        g_tw[t] = make_float2(cs, sn);
    }

    const float4* Kl4 = reinterpret_cast<const float4*>(K + (size_t)l * (Hc * Nc));

    float4 kv[16];
    #pragma unroll
    for (int r = 0; r < 16; ++r)
        kv[r] = __ldcs(Kl4 + (h0 + r) * (Nc / 4) + lane);

    float s[16];
    #pragma unroll
    for (int r = 0; r < 16; ++r) {
        const float4 c4 = reinterpret_cast<const float4*>(C + (h0 + r) * Nc)[lane];
        s[r] = c4.x * kv[r].x + c4.y * kv[r].y + c4.z * kv[r].z + c4.w * kv[r].w;
    }
    #pragma unroll
    for (int r = 0; r < 16; ++r) {
        #pragma unroll
        for (int o = 16; o > 0; o >>= 1)
            s[r] += __shfl_xor_sync(0xFFFFFFFFu, s[r], o);
    }
    if (lane == 0) {
        #pragma unroll
        for (int r = 0; r < 16; ++r) sKl[h0 + r] = s[r];
    }
    __syncthreads();

    if (threadIdx.x < 128)
        g_KlT[l * Hc + threadIdx.x] = sKl[threadIdx.x];
}

// ---------------------------------------------------------------------------
__device__ __forceinline__ float2 twiddle(const float2* stw, int t) {
    float2 w = stw[t & 1023];
    if (t & 1024) w = make_float2(w.y, -w.x);   // W[t+1024] = W[t] * (-i)
    return w;
}
__device__ __forceinline__ float2 cmul(float2 a, float2 b) {
    return make_float2(a.x * b.x - a.y * b.y, a.x * b.y + a.y * b.x);
}
__device__ __forceinline__ float2 cadd(float2 a, float2 b) {
    return make_float2(a.x + b.x, a.y + b.y);
}
__device__ __forceinline__ float2 csub(float2 a, float2 b) {
    return make_float2(a.x - b.x, a.y - b.y);
}

// ---------------------------------------------------------------------------
// Kernel 2: FFT convolution, 512 threads, radix-8 fused stages.
//   forward: 4 fused stages (12 radix-2 DIF), natural -> bit-rev
//   Hermitian unpack + pointwise (bit-rev order)
//   inverse: 4 fused stages (12 radix-2 DIT), bit-rev -> natural
// Each thread owns one disjoint 8-element octet per fused stage; all 8 loads
// batched, butterflies in registers, 8 stores. Skewed layout kills the
// small-stride bank conflicts. smem: 34.8KB data + 8KB twiddles = 42.8KB.
// ---------------------------------------------------------------------------
__global__ __launch_bounds__(512) void fftconv_kernel(
    const float* __restrict__ u,   // (H,L)
    const float* __restrict__ D,   // (H,)
    float* __restrict__ y)         // (H,L)
{
    __shared__ float2 sd[4352];    // 34.8 KB (skewed NF)
    __shared__ float2 stw[1024];   // 8 KB

    const int h   = blockIdx.x;
    const int tid = threadIdx.x;

    #pragma unroll
    for (int r = 0; r < 2; ++r)
        stw[tid + 512 * r] = g_tw[tid + 512 * r];

    // load z = u + i*k
    const float* uh = u + h * Lc;
    for (int n = tid; n < Lc; n += 512)
        sd[LOC(n)] = make_float2(uh[n], g_KlT[n * Hc + h]);
    for (int n = Lc + tid; n < NF; n += 512)
        sd[LOC(n)] = make_float2(0.0f, 0.0f);
    __syncthreads();

    // ---- forward: 4 fused radix-8 DIF stages (radix-2 stages 3f..3f+2) ----
    #pragma unroll 1
    for (int f = 0; f < 4; ++f) {
        const int s   = 3 * f;
        const int shq = 9 - 3 * f;
        const int q   = 1 << shq;
        const int j   = tid & (q - 1);
        const int g   = tid >> shq;
        const int m   = (g << (shq + 3)) | j;

        float2 x[8];
        #pragma unroll
        for (int k = 0; k < 8; ++k) x[k] = sd[LOC(m + k * q)];

        const float2 T1 = twiddle(stw, j << s);
        const float2 T2 = twiddle(stw, j << (s + 1));
        const float2 T3 = twiddle(stw, j << (s + 2));
        const float2 w8  = make_float2(0.70710678118655f, -0.70710678118655f);
        const float2 T1b = cmul(T1, w8);                    // T1*W512
        const float2 T1c = make_float2(T1.y, -T1.x);        // T1*(-i)
        const float2 T1d = make_float2(T1b.y, -T1b.x);      // T1*W512*(-i)
        const float2 T2m = make_float2(T2.y, -T2.x);        // T2*(-i)

        // layer A (stage s, pair distance 4q)
        const float2 a0 = cadd(x[0], x[4]);
        const float2 a1 = cadd(x[1], x[5]);
        const float2 a2 = cadd(x[2], x[6]);
        const float2 a3 = cadd(x[3], x[7]);
        const float2 b0 = cmul(csub(x[0], x[4]), T1);
        const float2 b1 = cmul(csub(x[1], x[5]), T1b);
        const float2 b2 = cmul(csub(x[2], x[6]), T1c);
        const float2 b3 = cmul(csub(x[3], x[7]), T1d);
        // layer B (stage s+1, distance 2q)
        const float2 A0 = cadd(a0, a2), A2 = cmul(csub(a0, a2), T2);
        const float2 A1 = cadd(a1, a3), A3 = cmul(csub(a1, a3), T2m);
        const float2 B0 = cadd(b0, b2), B2 = cmul(csub(b0, b2), T2);
        const float2 B1 = cadd(b1, b3), B3 = cmul(csub(b1, b3), T2m);
        // layer C (stage s+2, distance q)
        x[0] = cadd(A0, A1); x[1] = cmul(csub(A0, A1), T3);
        x[2] = cadd(A2, A3); x[3] = cmul(csub(A2, A3), T3);
        x[4] = cadd(B0, B1); x[5] = cmul(csub(B0, B1), T3);
        x[6] = cadd(B2, B3); x[7] = cmul(csub(B2, B3), T3);

        #pragma unroll
        for (int k = 0; k < 8; ++k) sd[LOC(m + k * q)] = x[k];
        __syncthreads();
    }

    // ---- Hermitian unpack + pointwise multiply (bit-reversed order) ----
    for (int fq = tid; fq <= NF / 2; fq += 512) {
        const int ia = __brev(fq) >> 20;
        const int ib = __brev((NF - fq) & (NF - 1)) >> 20;
        const float2 Za = sd[LOC(ia)];
        const float2 Zb = sd[LOC(ib)];
        const float2 U  = make_float2(0.5f * (Za.x + Zb.x), 0.5f * (Za.y - Zb.y));
        const float2 Kv = make_float2(0.5f * (Za.y + Zb.y), 0.5f * (Zb.x - Za.x));
        const float2 Y  = cmul(U, Kv);
        sd[LOC(ia)] = Y;
        sd[LOC(ib)] = make_float2(Y.x, -Y.y);
    }
    __syncthreads();

    // ---- inverse: 4 fused radix-8 DIT stages (radix-2 stages 11-3f..9-3f) --
    #pragma unroll 1
    for (int f = 0; f < 4; ++f) {
        const int shq = 3 * f;
        const int q   = 1 << shq;
        const int sA  = 11 - 3 * f;
        const int sB  = 10 - 3 * f;
        const int sC  = 9 - 3 * f;
        const int j   = tid & (q - 1);
        const int g   = tid >> shq;
        const int m   = (g << (shq + 3)) | j;

        float2 x[8];
        #pragma unroll
        for (int k = 0; k < 8; ++k) x[k] = sd[LOC(m + k * q)];

        float2 WA = twiddle(stw, j << sA);  WA.y = -WA.y;
        float2 WB = twiddle(stw, j << sB);  WB.y = -WB.y;
        float2 WC = twiddle(stw, j << sC);  WC.y = -WC.y;
        const float2 WB2 = make_float2(-WB.y, WB.x);        // WB*i
        const float2 w8c = make_float2(0.70710678118655f, 0.70710678118655f);
        const float2 WC1 = cmul(WC, w8c);                   // WC*conj(W512)
        const float2 WC2 = make_float2(-WC.y, WC.x);        // WC*i
        const float2 WC3 = make_float2(-WC1.y, WC1.x);      // WC1*i

        float2 t;
        // stage sA (distance q)
        t = cmul(x[1], WA); const float2 y0 = cadd(x[0], t), y1 = csub(x[0], t);
        t = cmul(x[3], WA); const float2 y2 = cadd(x[2], t), y3 = csub(x[2], t);
        t = cmul(x[5], WA); const float2 y4 = cadd(x[4], t), y5 = csub(x[4], t);
        t = cmul(x[7], WA); const float2 y6 = cadd(x[6], t), y7 = csub(x[6], t);
        // stage sB (distance 2q)
        t = cmul(y2, WB);  const float2 z0 = cadd(y0, t), z2 = csub(y0, t);
        t = cmul(y3, WB2); const float2 z1 = cadd(y1, t), z3 = csub(y1, t);
        t = cmul(y6, WB);  const float2 z4 = cadd(y4, t), z6 = csub(y4, t);
        t = cmul(y7, WB2); const float2 z5 = cadd(y5, t), z7 = csub(y5, t);
        // stage sC (distance 4q)
        t = cmul(z4, WC);  x[0] = cadd(z0, t); x[4] = csub(z0, t);
        t = cmul(z5, WC1); x[1] = cadd(z1, t); x[5] = csub(z1, t);
        t = cmul(z6, WC2); x[2] = cadd(z2, t); x[6] = csub(z2, t);
        t = cmul(z7, WC3); x[3] = cadd(z3, t); x[7] = csub(z3, t);

        #pragma unroll
        for (int k = 0; k < 8; ++k) sd[LOC(m + k * q)] = x[k];
        __syncthreads();
    }

    // ---- 'same' slice + 1/N scale + skip connection ----
    const float dh    = D[h];
    const float scale = 1.0f / (float)NF;
    for (int t2 = tid; t2 < Lc; t2 += 512)
        y[h * Lc + t2] = sd[LOC(t2 + 1023)].x * scale + dh * uh[t2];
}

// ---------------------------------------------------------------------------
extern "C" void kernel_launch(void* const* d_in, const int* in_sizes, int n_in,
                              void* d_out, int out_size)
{
    const float* u = nullptr;
    const float* C = nullptr;
    const float* D = nullptr;
    const float* K = nullptr;
    for (int i = 0; i < n_in; ++i) {
        switch (in_sizes[i]) {
            case Hc * Lc:  u = (const float*)d_in[i]; break;
            case Hc * Nc:  C = (const float*)d_in[i]; break;
            case Hc:       D = (const float*)d_in[i]; break;
            default:
                if (in_sizes[i] == Lc * Hc * Nc) K = (const float*)d_in[i];
                break;
        }
    }

    float* y = (float*)d_out;

    kl_synth_kernel<<<Lc, 256>>>(K, C);   // also builds twiddle table
    fftconv_kernel<<<Hc, 512>>>(u, D, y);
}